// round 12
// baseline (speedup 1.0000x reference)
#include <cuda_runtime.h>
#include <cuda_fp16.h>
#include <cuda_pipeline.h>
#include <cstdint>
#include <float.h>

#define NGRAPH 1024
#define HDIM   64
#define NMAX   1000000
#define CTAS   296        // 2 x 148 SMs -> one balanced wave at occ 2
#define NTHR   256
#define NW     8          // warps per CTA
#define NQ     64         // quads per CTA

// ---------------- device scratch (no allocation allowed) ----------------
__device__ float4 d_WL[32 * 256];    // packed LSTM weights: K=128 (h folded), [k4][n]
__device__ float  d_bsum[256];       // b_ih + b_hh
__device__ float4 d_W1p[32 * 256];   // W1 packed [k4][n]
__device__ float4 d_W2p[64 * 128];   // W2 packed [k4][n]
__device__ int    d_seg[NGRAPH + 1]; // segment row offsets
__device__ uint4  d_xh[NMAX * 8];    // fp16 copy of x (row = 64 halves = 8 uint4)

// dynamic shared memory layout
struct Smem {
    char  stage[NW][8192];  // per-warp double buffer: 2 x 4KB slices
    float s_act[4][128];    // per graph slot: [h(64) | r(64)]
    float s_c[4][64];
    float s_g[4][256];      // gates; s_g[0] reused as MLP hidden
    float s_rm[NQ];
    float s_rs[NQ];
    float s_rmn[NQ];        // per-quad max row-norm^2 partials (step 0)
    float s_mn[4];          // per graph max row-norm^2
    float s_M[4];           // per graph fixed softmax shift
    float s_rR[NQ][64];
};

// ---------------- prep: segment offsets + weight packing ----------------
__global__ void prep_kernel(const int* __restrict__ batch, int n,
                            const float* __restrict__ Wih, const float* __restrict__ Whh,
                            const float* __restrict__ bih, const float* __restrict__ bhh,
                            const float* __restrict__ W1,  const float* __restrict__ W2) {
    int t = blockIdx.x * blockDim.x + threadIdx.x;
    if (t < n) {
        int b = batch[t];
        b = min(max(b, 0), NGRAPH - 1);
        int bp;
        if (t == 0) bp = -1;
        else {
            bp = batch[t - 1];
            bp = min(max(bp, 0), NGRAPH - 1);
        }
        for (int v = bp + 1; v <= b; v++) d_seg[v] = t;
        if (t == n - 1) {
            for (int v = b + 1; v <= NGRAPH; v++) d_seg[v] = n;
        }
    }
    // gates = h @ (W_ih[:, :64] + W_hh).T + r @ W_ih[:, 64:].T + (b_ih + b_hh)
    if (t < 32 * 256) {
        int k4 = t >> 8, nn = t & 255;
        float4 w; float* wp = (float*)&w;
        #pragma unroll
        for (int j = 0; j < 4; j++) {
            int k = k4 * 4 + j;
            if (k < 64) wp[j] = Wih[nn * 128 + k] + Whh[nn * 64 + k];
            else        wp[j] = Wih[nn * 128 + k];
        }
        d_WL[t] = w;
        float4 w1; float* w1p = (float*)&w1;
        #pragma unroll
        for (int j = 0; j < 4; j++) w1p[j] = W1[nn * 128 + k4 * 4 + j];
        d_W1p[t] = w1;
    }
    if (t < 256) d_bsum[t] = bih[t] + bhh[t];
    if (t < 64 * 128) {
        int k4 = t >> 7, nn = t & 127;
        float4 w; float* wp = (float*)&w;
        #pragma unroll
        for (int j = 0; j < 4; j++) wp[j] = W2[nn * 256 + k4 * 4 + j];
        d_W2p[t] = w;
    }
}

__device__ __forceinline__ float sigmoidf_(float v) {
    return 1.0f / (1.0f + __expf(-v));
}

// fill one 4KB slice (fp32: 16 rows, fp16: 32 rows) via cp.async
template<bool FIRST>
__device__ __forceinline__ void fill_slice(char* slot, const float* __restrict__ x,
                                           int srow0, int r1, int lane) {
    if (FIRST) {
        int row = srow0 + (lane >> 1);
        row = min(row, r1 - 1);
        const char* g = (const char*)(x + (size_t)row * HDIM) + (lane & 1) * 128;
        char* sdst = slot + (lane >> 1) * 256 + (lane & 1) * 128;
        #pragma unroll
        for (int u = 0; u < 8; u++)
            __pipeline_memcpy_async(sdst + u * 16, g + u * 16, 16);
    } else {
        int row = srow0 + lane;
        row = min(row, r1 - 1);
        const char* g = (const char*)(&d_xh[(size_t)row * 8]);
        char* sdst = slot + lane * 128;
        #pragma unroll
        for (int u = 0; u < 8; u++)
            __pipeline_memcpy_async(sdst + u * 16, g + u * 16, 16);
    }
}

// unpack a 32B fp16 chunk (2 uint4) into 16 floats
__device__ __forceinline__ void unpack16(const char* p, float4& v0, float4& v1,
                                         float4& v2, float4& v3) {
    union { uint4 u; __half2 h[4]; } pk0, pk1;
    pk0.u = ((const uint4*)p)[0];
    pk1.u = ((const uint4*)p)[1];
    float2 f;
    f = __half22float2(pk0.h[0]); v0.x = f.x; v0.y = f.y;
    f = __half22float2(pk0.h[1]); v0.z = f.x; v0.w = f.y;
    f = __half22float2(pk0.h[2]); v1.x = f.x; v1.y = f.y;
    f = __half22float2(pk0.h[3]); v1.z = f.x; v1.w = f.y;
    f = __half22float2(pk1.h[0]); v2.x = f.x; v2.y = f.y;
    f = __half22float2(pk1.h[1]); v2.z = f.x; v2.w = f.y;
    f = __half22float2(pk1.h[2]); v3.x = f.x; v3.y = f.y;
    f = __half22float2(pk1.h[3]); v3.z = f.x; v3.w = f.y;
}

__device__ __forceinline__ float dot16(const float4& v0, const float4& v1,
                                       const float4& v2, const float4& v3,
                                       const float4& q0, const float4& q1,
                                       const float4& q2, const float4& q3) {
    return v0.x * q0.x + v0.y * q0.y + v0.z * q0.z + v0.w * q0.w
         + v1.x * q1.x + v1.y * q1.y + v1.z * q1.z + v1.w * q1.w
         + v2.x * q2.x + v2.y * q2.y + v2.z * q2.z + v2.w * q2.w
         + v3.x * q3.x + v3.y * q3.y + v3.z * q3.z + v3.w * q3.w;
}

__device__ __forceinline__ void acc16(float& s, float4& R0, float4& R1, float4& R2, float4& R3,
                                      float d, const float4& v0, const float4& v1,
                                      const float4& v2, const float4& v3) {
    s += d;
    R0.x += d * v0.x; R0.y += d * v0.y; R0.z += d * v0.z; R0.w += d * v0.w;
    R1.x += d * v1.x; R1.y += d * v1.y; R1.z += d * v1.z; R1.w += d * v1.w;
    R2.x += d * v2.x; R2.y += d * v2.y; R2.z += d * v2.z; R2.w += d * v2.w;
    R3.x += d * v3.x; R3.y += d * v3.y; R3.z += d * v3.z; R3.w += d * v3.w;
}

// step-0 slice consumer: 16 rows, quad owns rows {q, 8+q}; online softmax + norms + fp16 store
__device__ __forceinline__ void consume_slice_first(const char* slot, int srow, int r1,
        int q, int ql,
        const float4& q0, const float4& q1, const float4& q2, const float4& q3,
        float& m, float& s, float& mn,
        float4& R0, float4& R1, float4& R2, float4& R3) {
    const int ra = srow + q, rb = srow + 8 + q;
    const float4* pa = (const float4*)(slot + q * 256 + ql * 64);
    const float4* pb = (const float4*)(slot + (8 + q) * 256 + ql * 64);
    float4 a0 = pa[0], a1 = pa[1], a2 = pa[2], a3 = pa[3];
    float4 b0 = pb[0], b1 = pb[1], b2 = pb[2], b3 = pb[3];
    // fp16 copies
    if (ra < r1) {
        union { uint4 u; __half2 h[4]; } k0, k1;
        k0.h[0] = __floats2half2_rn(a0.x, a0.y);
        k0.h[1] = __floats2half2_rn(a0.z, a0.w);
        k0.h[2] = __floats2half2_rn(a1.x, a1.y);
        k0.h[3] = __floats2half2_rn(a1.z, a1.w);
        k1.h[0] = __floats2half2_rn(a2.x, a2.y);
        k1.h[1] = __floats2half2_rn(a2.z, a2.w);
        k1.h[2] = __floats2half2_rn(a3.x, a3.y);
        k1.h[3] = __floats2half2_rn(a3.z, a3.w);
        __stcs(&d_xh[(size_t)ra * 8 + 2 * ql],     k0.u);
        __stcs(&d_xh[(size_t)ra * 8 + 2 * ql + 1], k1.u);
    }
    if (rb < r1) {
        union { uint4 u; __half2 h[4]; } k0, k1;
        k0.h[0] = __floats2half2_rn(b0.x, b0.y);
        k0.h[1] = __floats2half2_rn(b0.z, b0.w);
        k0.h[2] = __floats2half2_rn(b1.x, b1.y);
        k0.h[3] = __floats2half2_rn(b1.z, b1.w);
        k1.h[0] = __floats2half2_rn(b2.x, b2.y);
        k1.h[1] = __floats2half2_rn(b2.z, b2.w);
        k1.h[2] = __floats2half2_rn(b3.x, b3.y);
        k1.h[3] = __floats2half2_rn(b3.z, b3.w);
        __stcs(&d_xh[(size_t)rb * 8 + 2 * ql],     k0.u);
        __stcs(&d_xh[(size_t)rb * 8 + 2 * ql + 1], k1.u);
    }
    float pA = dot16(a0, a1, a2, a3, q0, q1, q2, q3);
    float pB = dot16(b0, b1, b2, b3, q0, q1, q2, q3);
    float nA = dot16(a0, a1, a2, a3, a0, a1, a2, a3);
    float nB = dot16(b0, b1, b2, b3, b0, b1, b2, b3);
    pA += __shfl_xor_sync(0xffffffffu, pA, 1);
    pB += __shfl_xor_sync(0xffffffffu, pB, 1);
    nA += __shfl_xor_sync(0xffffffffu, nA, 1);
    nB += __shfl_xor_sync(0xffffffffu, nB, 1);
    pA += __shfl_xor_sync(0xffffffffu, pA, 2);
    pB += __shfl_xor_sync(0xffffffffu, pB, 2);
    nA += __shfl_xor_sync(0xffffffffu, nA, 2);
    nB += __shfl_xor_sync(0xffffffffu, nB, 2);
    const bool actA = (ra < r1), actB = (rb < r1);
    if (actA) mn = fmaxf(mn, nA);
    if (actB) mn = fmaxf(mn, nB);
    float P = actB ? fmaxf(pA, pB) : pA;   // actA always true when called (iters guard)
    if (P > m) {
        float sc = __expf(m - P);
        s *= sc;
        R0.x *= sc; R0.y *= sc; R0.z *= sc; R0.w *= sc;
        R1.x *= sc; R1.y *= sc; R1.z *= sc; R1.w *= sc;
        R2.x *= sc; R2.y *= sc; R2.z *= sc; R2.w *= sc;
        R3.x *= sc; R3.y *= sc; R3.z *= sc; R3.w *= sc;
        m = P;
    }
    float dA = actA ? __expf(pA - m) : 0.0f;
    float dB = actB ? __expf(pB - m) : 0.0f;
    acc16(s, R0, R1, R2, R3, dA, a0, a1, a2, a3);
    acc16(s, R0, R1, R2, R3, dB, b0, b1, b2, b3);
}

// steps 1-4 slice consumer: 32 rows, quad owns {q, 8+q, 16+q, 24+q}; fixed shift M
__device__ __forceinline__ void consume_slice_fixed(const char* slot, int srow, int r1,
        int q, int ql, float M,
        const float4& q0, const float4& q1, const float4& q2, const float4& q3,
        float& s, float4& R0, float4& R1, float4& R2, float4& R3) {
    #pragma unroll
    for (int g = 0; g < 2; g++) {
        const int ra = srow + 16 * g + q, rb = srow + 16 * g + 8 + q;
        float4 a0, a1, a2, a3, b0, b1, b2, b3;
        unpack16(slot + (16 * g + q) * 128 + ql * 32,     a0, a1, a2, a3);
        unpack16(slot + (16 * g + 8 + q) * 128 + ql * 32, b0, b1, b2, b3);
        float pA = dot16(a0, a1, a2, a3, q0, q1, q2, q3);
        float pB = dot16(b0, b1, b2, b3, q0, q1, q2, q3);
        pA += __shfl_xor_sync(0xffffffffu, pA, 1);
        pB += __shfl_xor_sync(0xffffffffu, pB, 1);
        pA += __shfl_xor_sync(0xffffffffu, pA, 2);
        pB += __shfl_xor_sync(0xffffffffu, pB, 2);
        float dA = (ra < r1) ? __expf(pA - M) : 0.0f;
        float dB = (rb < r1) ? __expf(pB - M) : 0.0f;
        acc16(s, R0, R1, R2, R3, dA, a0, a1, a2, a3);
        acc16(s, R0, R1, R2, R3, dB, b0, b1, b2, b3);
    }
}

// per-warp streaming pass: 4KB double-buffered cp.async ring (no block syncs inside)
template<bool FIRST>
__device__ __forceinline__ void attn_pass(const float* __restrict__ x, char* wstage,
        int r0, int r1, int w, int lane, int q, int ql, float M,
        const float4& q0, const float4& q1, const float4& q2, const float4& q3,
        float& m, float& s, float& mn,
        float4& R0, float4& R1, float4& R2, float4& R3) {
    constexpr int ROWS   = FIRST ? 16 : 32;
    constexpr int STRIDE = NW * ROWS;
    const int wrow0 = r0 + w * ROWS;
    const int iters = (r1 > wrow0) ? ((r1 - wrow0 + STRIDE - 1) / STRIDE) : 0;
    if (iters > 0) fill_slice<FIRST>(wstage, x, wrow0, r1, lane);
    __pipeline_commit();
    for (int j = 0; j < iters; j++) {
        int slot = j & 1;
        if (j + 1 < iters)
            fill_slice<FIRST>(wstage + (slot ^ 1) * 4096, x, wrow0 + (j + 1) * STRIDE, r1, lane);
        __pipeline_commit();
        __pipeline_wait_prior(1);      // slice j ready
        int srow = wrow0 + j * STRIDE;
        if (FIRST)
            consume_slice_first(wstage + slot * 4096, srow, r1, q, ql,
                                q0, q1, q2, q3, m, s, mn, R0, R1, R2, R3);
        else
            consume_slice_fixed(wstage + slot * 4096, srow, r1, q, ql, M,
                                q0, q1, q2, q3, s, R0, R1, R2, R3);
        __syncwarp();                  // all lanes done with slot before refill
    }
    __pipeline_wait_prior(0);
}

// ---------------- fused Set2Set + MLP: 296 CTAs, dynamic graph partition ----------------
__global__ __launch_bounds__(NTHR, 2)
void fused_kernel(const float* __restrict__ x,
                  const float* __restrict__ b1,
                  const float* __restrict__ b2,
                  float* __restrict__ out, int n) {
    extern __shared__ char smraw[];
    Smem& S = *(Smem*)smraw;

    const int t    = threadIdx.x;
    const int c    = blockIdx.x;
    const int w    = t >> 5;          // warp 0..7
    const int lane = t & 31;
    const int q    = lane >> 2;       // quad within warp 0..7
    const int ql   = t & 3;           // lane within quad
    const int qd   = t >> 2;          // global quad 0..63
    char* wstage   = S.stage[w];

    const int g0  = (c * NGRAPH) / CTAS;
    const int g1  = ((c + 1) * NGRAPH) / CTAS;
    const int ngr = g1 - g0;          // 3 or 4

    if (t < 128) {
        #pragma unroll
        for (int gi = 0; gi < 4; gi++) {
            S.s_act[gi][t] = 0.0f;
            if (t < 64) S.s_c[gi][t] = 0.0f;
        }
    }
    if (t < 4) { S.s_mn[t] = 0.0f; S.s_M[t] = 0.0f; }
    int row0[4], row1[4];
    #pragma unroll
    for (int gi = 0; gi < 4; gi++) {
        int gg = min(g0 + gi, NGRAPH - 1);
        int a = d_seg[gg];
        int b = d_seg[gg + 1];
        a = min(max(a, 0), n);
        b = min(max(b, a), n);
        row0[gi] = a;
        row1[gi] = b;
    }
    __syncthreads();

    for (int step = 0; step < 5; step++) {
        // ---- LSTM gates: 256 threads = 256 gates, all graph slots per thread ----
        {
            float acc0 = d_bsum[t], acc1 = acc0, acc2 = acc0, acc3 = acc0;
            const float4* a0 = (const float4*)S.s_act[0];
            const float4* a1 = (const float4*)S.s_act[1];
            const float4* a2 = (const float4*)S.s_act[2];
            const float4* a3 = (const float4*)S.s_act[3];
            #pragma unroll 8
            for (int k4 = 0; k4 < 32; k4++) {
                float4 wv = d_WL[k4 * 256 + t];
                float4 v0 = a0[k4];
                float4 v1 = a1[k4];
                float4 v2 = a2[k4];
                float4 v3 = a3[k4];
                acc0 += wv.x * v0.x + wv.y * v0.y + wv.z * v0.z + wv.w * v0.w;
                acc1 += wv.x * v1.x + wv.y * v1.y + wv.z * v1.z + wv.w * v1.w;
                acc2 += wv.x * v2.x + wv.y * v2.y + wv.z * v2.z + wv.w * v2.w;
                acc3 += wv.x * v3.x + wv.y * v3.y + wv.z * v3.z + wv.w * v3.w;
            }
            S.s_g[0][t] = acc0;
            S.s_g[1][t] = acc1;
            S.s_g[2][t] = acc2;
            S.s_g[3][t] = acc3;
        }
        __syncthreads();
        {
            const int gi = t >> 6, k = t & 63;
            float gc = sigmoidf_(S.s_g[gi][k]);
            float gf = sigmoidf_(S.s_g[gi][64 + k]);
            float gg = tanhf(S.s_g[gi][128 + k]);
            float go = sigmoidf_(S.s_g[gi][192 + k]);
            float cc = gf * S.s_c[gi][k] + gc * gg;
            S.s_c[gi][k] = cc;
            S.s_act[gi][k] = go * tanhf(cc);       // h (== q)
        }
        __syncthreads();
        if (step > 0) {
            // fixed shift for this step: M = ||q|| * sqrt(max row-norm^2)
            if (t < 4) {
                float q2 = 0.0f;
                #pragma unroll 16
                for (int k = 0; k < 64; k++) {
                    float hv = S.s_act[t][k];
                    q2 += hv * hv;
                }
                S.s_M[t] = sqrtf(q2 * S.s_mn[t]);
            }
            __syncthreads();
        }

        // ---- attention per graph: pipelined streaming pass ----
        for (int gi = 0; gi < ngr; gi++) {
            const float4 q0 = ((const float4*)S.s_act[gi])[4 * ql];
            const float4 q1 = ((const float4*)S.s_act[gi])[4 * ql + 1];
            const float4 q2 = ((const float4*)S.s_act[gi])[4 * ql + 2];
            const float4 q3 = ((const float4*)S.s_act[gi])[4 * ql + 3];
            const float M = S.s_M[gi];
            float m = -FLT_MAX, s = 0.0f, mn = 0.0f;
            float4 R0 = make_float4(0.f, 0.f, 0.f, 0.f);
            float4 R1 = R0, R2 = R0, R3 = R0;

            if (step == 0)
                attn_pass<true >(x, wstage, row0[gi], row1[gi], w, lane, q, ql, M,
                                 q0, q1, q2, q3, m, s, mn, R0, R1, R2, R3);
            else
                attn_pass<false>(x, wstage, row0[gi], row1[gi], w, lane, q, ql, M,
                                 q0, q1, q2, q3, m, s, mn, R0, R1, R2, R3);

            // combine NQ quad partials
            if (ql == 0) {
                S.s_rm[qd]  = (step == 0) ? m : M;
                S.s_rs[qd]  = s;
                S.s_rmn[qd] = mn;
            }
            ((float4*)S.s_rR[qd])[4 * ql]     = R0;
            ((float4*)S.s_rR[qd])[4 * ql + 1] = R1;
            ((float4*)S.s_rR[qd])[4 * ql + 2] = R2;
            ((float4*)S.s_rR[qd])[4 * ql + 3] = R3;
            __syncthreads();
            if (t < 64) {
                float Mx = -FLT_MAX;
                #pragma unroll 16
                for (int p = 0; p < NQ; p++) Mx = fmaxf(Mx, S.s_rm[p]);
                float st = 0.0f, Rk = 0.0f;
                #pragma unroll 16
                for (int p = 0; p < NQ; p++) {
                    float wq = __expf(S.s_rm[p] - Mx);
                    st += wq * S.s_rs[p];
                    Rk += wq * S.s_rR[p][t];
                }
                S.s_act[gi][64 + t] = Rk / fmaxf(st, 1e-16f);   // r
                if (step == 0 && t == 0) {
                    float mnx = 0.0f;
                    #pragma unroll 16
                    for (int p = 0; p < NQ; p++) mnx = fmaxf(mnx, S.s_rmn[p]);
                    S.s_mn[gi] = mnx;
                }
            }
            __syncthreads();
        }
    }

    // ---- final MLP per graph: 128 -> 256 (relu) -> 128 ----
    for (int gi = 0; gi < ngr; gi++) {
        {
            float acc = b1[t];
            const float4* a = (const float4*)S.s_act[gi];
            #pragma unroll 8
            for (int k4 = 0; k4 < 32; k4++) {
                float4 wv = d_W1p[k4 * 256 + t];
                float4 v  = a[k4];
                acc += wv.x * v.x + wv.y * v.y + wv.z * v.z + wv.w * v.w;
            }
            S.s_g[0][t] = fmaxf(acc, 0.0f);
        }
        __syncthreads();
        if (t < 128) {
            float acc = b2[t];
            const float4* hv = (const float4*)S.s_g[0];
            #pragma unroll 8
            for (int k4 = 0; k4 < 64; k4++) {
                float4 wv = d_W2p[k4 * 128 + t];
                float4 v  = hv[k4];
                acc += wv.x * v.x + wv.y * v.y + wv.z * v.z + wv.w * v.w;
            }
            out[(size_t)(g0 + gi) * 128 + t] = acc;
        }
        __syncthreads();
    }
}

extern "C" void kernel_launch(void* const* d_in, const int* in_sizes, int n_in,
                              void* d_out, int out_size) {
    const float* x     = (const float*)d_in[0];
    const int*   batch = (const int*)d_in[1];     // int32 (JAX x64 disabled)
    const float* Wih   = (const float*)d_in[2];
    const float* Whh   = (const float*)d_in[3];
    const float* bih   = (const float*)d_in[4];
    const float* bhh   = (const float*)d_in[5];
    const float* W1    = (const float*)d_in[6];
    const float* b1    = (const float*)d_in[7];
    const float* W2    = (const float*)d_in[8];
    const float* b2    = (const float*)d_in[9];

    int n = in_sizes[0] / HDIM;   // number of nodes

    static_assert(sizeof(Smem) <= 96 * 1024, "smem too big for occ 2");
    cudaFuncSetAttribute(fused_kernel, cudaFuncAttributeMaxDynamicSharedMemorySize,
                         (int)sizeof(Smem));

    prep_kernel<<<(n + 511) / 512, 512>>>(batch, n, Wih, Whh, bih, bhh, W1, W2);
    fused_kernel<<<CTAS, NTHR, sizeof(Smem)>>>(x, b1, b2, (float*)d_out, n);
}

// round 13
// speedup vs baseline: 1.5960x; 1.5960x over previous
#include <cuda_runtime.h>
#include <cuda_fp16.h>
#include <cuda_pipeline.h>
#include <cstdint>
#include <float.h>

#define NGRAPH 1024
#define HDIM   64
#define NMAX   1000000
#define CTAS   592        // 4 x 148 SMs -> one balanced wave at occ 4
#define NTHR   128
#define NW     4          // warps per CTA
#define NQ     32         // quads per CTA

// ---------------- device scratch (no allocation allowed) ----------------
__device__ float4 d_WL[32 * 256];    // packed LSTM weights: K=128 (h folded), [k4][n]
__device__ float  d_bsum[256];       // b_ih + b_hh
__device__ float4 d_W1p[32 * 256];   // W1 packed [k4][n]
__device__ float4 d_W2p[64 * 128];   // W2 packed [k4][n]
__device__ int    d_seg[NGRAPH + 1]; // segment row offsets
__device__ uint4  d_xh[NMAX * 8];    // fp16 copy of x (row = 64 halves = 8 uint4)

// dynamic shared memory layout (~37 KB -> 4 CTAs/SM)
struct Smem {
    char  stage[NW][6144];  // per-warp ring: fp32 3x2048B, fp16 6x1024B
    float s_act[2][128];    // per graph slot: [h(64) | r(64)]
    float s_c[2][64];
    float s_g[2][256];      // gates; s_g[0] reused as MLP hidden
    float s_rm[NQ];
    float s_rs[NQ];
    float s_rmn[NQ];        // per-quad max row-norm^2 partials (step 0)
    float s_mn[2];          // per graph max row-norm^2
    float s_M[2];           // per graph fixed softmax shift
    float s_rR[NQ][64];
};

// ---------------- prep: segment offsets + weight packing ----------------
__global__ void prep_kernel(const int* __restrict__ batch, int n,
                            const float* __restrict__ Wih, const float* __restrict__ Whh,
                            const float* __restrict__ bih, const float* __restrict__ bhh,
                            const float* __restrict__ W1,  const float* __restrict__ W2) {
    int t = blockIdx.x * blockDim.x + threadIdx.x;
    if (t < n) {
        int b = batch[t];
        b = min(max(b, 0), NGRAPH - 1);
        int bp;
        if (t == 0) bp = -1;
        else {
            bp = batch[t - 1];
            bp = min(max(bp, 0), NGRAPH - 1);
        }
        for (int v = bp + 1; v <= b; v++) d_seg[v] = t;
        if (t == n - 1) {
            for (int v = b + 1; v <= NGRAPH; v++) d_seg[v] = n;
        }
    }
    // gates = h @ (W_ih[:, :64] + W_hh).T + r @ W_ih[:, 64:].T + (b_ih + b_hh)
    if (t < 32 * 256) {
        int k4 = t >> 8, nn = t & 255;
        float4 w; float* wp = (float*)&w;
        #pragma unroll
        for (int j = 0; j < 4; j++) {
            int k = k4 * 4 + j;
            if (k < 64) wp[j] = Wih[nn * 128 + k] + Whh[nn * 64 + k];
            else        wp[j] = Wih[nn * 128 + k];
        }
        d_WL[t] = w;
        float4 w1; float* w1p = (float*)&w1;
        #pragma unroll
        for (int j = 0; j < 4; j++) w1p[j] = W1[nn * 128 + k4 * 4 + j];
        d_W1p[t] = w1;
    }
    if (t < 256) d_bsum[t] = bih[t] + bhh[t];
    if (t < 64 * 128) {
        int k4 = t >> 7, nn = t & 127;
        float4 w; float* wp = (float*)&w;
        #pragma unroll
        for (int j = 0; j < 4; j++) wp[j] = W2[nn * 256 + k4 * 4 + j];
        d_W2p[t] = w;
    }
}

__device__ __forceinline__ float sigmoidf_(float v) {
    return 1.0f / (1.0f + __expf(-v));
}

// fill one 8-row slice into a staging slot via cp.async
template<bool FIRST>
__device__ __forceinline__ void fill_slice(char* slot, const float* __restrict__ x,
                                           int srow0, int r1, int lane) {
    int row = srow0 + (lane >> 2);
    row = min(row, r1 - 1);              // clamp: real data for tail rows (guarded later)
    if (FIRST) {
        const char* g = (const char*)(x + (size_t)row * HDIM) + (lane & 3) * 64;
        char* sdst = slot + (lane >> 2) * 256 + (lane & 3) * 64;
        #pragma unroll
        for (int u = 0; u < 4; u++)
            __pipeline_memcpy_async(sdst + u * 16, g + u * 16, 16);
    } else {
        const char* g = (const char*)(&d_xh[(size_t)row * 8]) + (lane & 3) * 32;
        char* sdst = slot + (lane >> 2) * 128 + (lane & 3) * 32;
        #pragma unroll
        for (int u = 0; u < 2; u++)
            __pipeline_memcpy_async(sdst + u * 16, g + u * 16, 16);
    }
}

// step-0 consumer: online softmax + max row-norm^2 tracking + fp16 copy store
__device__ __forceinline__ void consume_row_first(const char* slot, int row, int r1,
        int q, int ql,
        const float4& q0, const float4& q1, const float4& q2, const float4& q3,
        float& m, float& s, float& mn,
        float4& R0, float4& R1, float4& R2, float4& R3) {
    const bool act = (row < r1);
    const float4* p4 = (const float4*)(slot + q * 256 + ql * 64);
    float4 v0 = p4[0], v1 = p4[1], v2 = p4[2], v3 = p4[3];
    if (act) {   // fp16 copy for steps 1-4
        union { uint4 u; __half2 h[4]; } pk0, pk1;
        pk0.h[0] = __floats2half2_rn(v0.x, v0.y);
        pk0.h[1] = __floats2half2_rn(v0.z, v0.w);
        pk0.h[2] = __floats2half2_rn(v1.x, v1.y);
        pk0.h[3] = __floats2half2_rn(v1.z, v1.w);
        pk1.h[0] = __floats2half2_rn(v2.x, v2.y);
        pk1.h[1] = __floats2half2_rn(v2.z, v2.w);
        pk1.h[2] = __floats2half2_rn(v3.x, v3.y);
        pk1.h[3] = __floats2half2_rn(v3.z, v3.w);
        __stcs(&d_xh[(size_t)row * 8 + 2 * ql],     pk0.u);
        __stcs(&d_xh[(size_t)row * 8 + 2 * ql + 1], pk1.u);
    }
    float p = v0.x * q0.x + v0.y * q0.y + v0.z * q0.z + v0.w * q0.w
            + v1.x * q1.x + v1.y * q1.y + v1.z * q1.z + v1.w * q1.w
            + v2.x * q2.x + v2.y * q2.y + v2.z * q2.z + v2.w * q2.w
            + v3.x * q3.x + v3.y * q3.y + v3.z * q3.z + v3.w * q3.w;
    float n2 = v0.x * v0.x + v0.y * v0.y + v0.z * v0.z + v0.w * v0.w
             + v1.x * v1.x + v1.y * v1.y + v1.z * v1.z + v1.w * v1.w
             + v2.x * v2.x + v2.y * v2.y + v2.z * v2.z + v2.w * v2.w
             + v3.x * v3.x + v3.y * v3.y + v3.z * v3.z + v3.w * v3.w;
    p  += __shfl_xor_sync(0xffffffffu, p, 1);
    n2 += __shfl_xor_sync(0xffffffffu, n2, 1);
    p  += __shfl_xor_sync(0xffffffffu, p, 2);
    n2 += __shfl_xor_sync(0xffffffffu, n2, 2);
    if (act) {
        mn = fmaxf(mn, n2);
        if (p > m) {
            float sc = __expf(m - p);
            s *= sc;
            R0.x *= sc; R0.y *= sc; R0.z *= sc; R0.w *= sc;
            R1.x *= sc; R1.y *= sc; R1.z *= sc; R1.w *= sc;
            R2.x *= sc; R2.y *= sc; R2.z *= sc; R2.w *= sc;
            R3.x *= sc; R3.y *= sc; R3.z *= sc; R3.w *= sc;
            m = p;
        }
        float d = __expf(p - m);
        s += d;
        R0.x += d * v0.x; R0.y += d * v0.y; R0.z += d * v0.z; R0.w += d * v0.w;
        R1.x += d * v1.x; R1.y += d * v1.y; R1.z += d * v1.z; R1.w += d * v1.w;
        R2.x += d * v2.x; R2.y += d * v2.y; R2.z += d * v2.z; R2.w += d * v2.w;
        R3.x += d * v3.x; R3.y += d * v3.y; R3.z += d * v3.z; R3.w += d * v3.w;
    }
}

// steps 1-4 consumer: FIXED shift M -> straight-line, no carried compare chain
__device__ __forceinline__ void consume_row_fixed(const char* slot, int row, int r1,
        int q, int ql, float M,
        const float4& q0, const float4& q1, const float4& q2, const float4& q3,
        float& s, float4& R0, float4& R1, float4& R2, float4& R3) {
    const uint4* p4 = (const uint4*)(slot + q * 128 + ql * 32);
    union { uint4 u; __half2 h[4]; } pk0, pk1;
    pk0.u = p4[0];
    pk1.u = p4[1];
    float2 f;
    float4 v0, v1, v2, v3;
    f = __half22float2(pk0.h[0]); v0.x = f.x; v0.y = f.y;
    f = __half22float2(pk0.h[1]); v0.z = f.x; v0.w = f.y;
    f = __half22float2(pk0.h[2]); v1.x = f.x; v1.y = f.y;
    f = __half22float2(pk0.h[3]); v1.z = f.x; v1.w = f.y;
    f = __half22float2(pk1.h[0]); v2.x = f.x; v2.y = f.y;
    f = __half22float2(pk1.h[1]); v2.z = f.x; v2.w = f.y;
    f = __half22float2(pk1.h[2]); v3.x = f.x; v3.y = f.y;
    f = __half22float2(pk1.h[3]); v3.z = f.x; v3.w = f.y;
    float p = v0.x * q0.x + v0.y * q0.y + v0.z * q0.z + v0.w * q0.w
            + v1.x * q1.x + v1.y * q1.y + v1.z * q1.z + v1.w * q1.w
            + v2.x * q2.x + v2.y * q2.y + v2.z * q2.z + v2.w * q2.w
            + v3.x * q3.x + v3.y * q3.y + v3.z * q3.z + v3.w * q3.w;
    p += __shfl_xor_sync(0xffffffffu, p, 1);
    p += __shfl_xor_sync(0xffffffffu, p, 2);
    float d = (row < r1) ? __expf(p - M) : 0.0f;
    s += d;
    R0.x += d * v0.x; R0.y += d * v0.y; R0.z += d * v0.z; R0.w += d * v0.w;
    R1.x += d * v1.x; R1.y += d * v1.y; R1.z += d * v1.z; R1.w += d * v1.w;
    R2.x += d * v2.x; R2.y += d * v2.y; R2.z += d * v2.z; R2.w += d * v2.w;
    R3.x += d * v3.x; R3.y += d * v3.y; R3.z += d * v3.z; R3.w += d * v3.w;
}

// per-warp streaming attention pass with cp.async ring (no block syncs inside)
template<bool FIRST>
__device__ __forceinline__ void attn_pass(const float* __restrict__ x, char* wstage,
        int r0, int r1, int w, int lane, int q, int ql, float M,
        const float4& q0, const float4& q1, const float4& q2, const float4& q3,
        float& m, float& s, float& mn,
        float4& R0, float4& R1, float4& R2, float4& R3) {
    constexpr int S      = FIRST ? 3 : 6;
    constexpr int SLICE  = FIRST ? 2048 : 1024;
    constexpr int STRIDE = NW * 8;    // 32 rows per ring step
    const int wrow0 = r0 + w * 8;
    const int iters = (r1 > wrow0) ? ((r1 - wrow0 + STRIDE - 1) / STRIDE) : 0;
    #pragma unroll
    for (int j = 0; j < S - 1; j++) {
        if (j < iters) fill_slice<FIRST>(wstage + j * SLICE, x, wrow0 + j * STRIDE, r1, lane);
        __pipeline_commit();
    }
    int slot = 0;
    for (int j = 0; j < iters; j++) {
        __pipeline_wait_prior(S - 2);
        // issue next fill BEFORE the compute chain (target slot consumed 1 iter ago)
        int jn = j + S - 1;
        int sn = slot + S - 1; if (sn >= S) sn -= S;
        if (jn < iters) fill_slice<FIRST>(wstage + sn * SLICE, x, wrow0 + jn * STRIDE, r1, lane);
        __pipeline_commit();
        if (FIRST)
            consume_row_first(wstage + slot * SLICE, wrow0 + j * STRIDE + q, r1, q, ql,
                              q0, q1, q2, q3, m, s, mn, R0, R1, R2, R3);
        else
            consume_row_fixed(wstage + slot * SLICE, wrow0 + j * STRIDE + q, r1, q, ql, M,
                              q0, q1, q2, q3, s, R0, R1, R2, R3);
        __syncwarp();            // all lanes done reading slot before it is refilled
        slot++; if (slot == S) slot = 0;
    }
    __pipeline_wait_prior(0);
}

// ---------------- fused Set2Set + MLP: 592 CTAs x 128 thr, 1-2 graphs each ----------------
__global__ __launch_bounds__(NTHR, 4)
void fused_kernel(const float* __restrict__ x,
                  const float* __restrict__ b1,
                  const float* __restrict__ b2,
                  float* __restrict__ out, int n) {
    extern __shared__ char smraw[];
    Smem& S = *(Smem*)smraw;

    const int t    = threadIdx.x;
    const int c    = blockIdx.x;
    const int w    = t >> 5;          // warp 0..3
    const int lane = t & 31;
    const int q    = lane >> 2;       // quad within warp 0..7
    const int ql   = t & 3;           // lane within quad
    const int qd   = t >> 2;          // global quad 0..31
    char* wstage   = S.stage[w];

    const int g0  = (c * NGRAPH) / CTAS;
    const int g1  = ((c + 1) * NGRAPH) / CTAS;
    const int ngr = g1 - g0;          // 1 or 2

    #pragma unroll
    for (int gi = 0; gi < 2; gi++) {
        S.s_act[gi][t] = 0.0f;
        if (t < 64) S.s_c[gi][t] = 0.0f;
    }
    if (t < 2) { S.s_mn[t] = 0.0f; S.s_M[t] = 0.0f; }
    int row0[2], row1[2];
    #pragma unroll
    for (int gi = 0; gi < 2; gi++) {
        int gg = min(g0 + gi, NGRAPH - 1);
        int a = d_seg[gg];
        int b = d_seg[gg + 1];
        a = min(max(a, 0), n);
        b = min(max(b, a), n);
        row0[gi] = a;
        row1[gi] = b;
    }
    __syncthreads();

    for (int step = 0; step < 5; step++) {
        // ---- LSTM gates: 128 threads x 2 gate-cols x 2 graph slots ----
        {
            float acc00 = d_bsum[t], acc01 = d_bsum[t + 128];
            float acc10 = acc00, acc11 = acc01;
            const float4* a0 = (const float4*)S.s_act[0];
            const float4* a1 = (const float4*)S.s_act[1];
            #pragma unroll 8
            for (int k4 = 0; k4 < 32; k4++) {
                float4 w0 = d_WL[k4 * 256 + t];
                float4 w1 = d_WL[k4 * 256 + t + 128];
                float4 v0 = a0[k4];
                float4 v1 = a1[k4];
                acc00 += w0.x * v0.x + w0.y * v0.y + w0.z * v0.z + w0.w * v0.w;
                acc01 += w1.x * v0.x + w1.y * v0.y + w1.z * v0.z + w1.w * v0.w;
                acc10 += w0.x * v1.x + w0.y * v1.y + w0.z * v1.z + w0.w * v1.w;
                acc11 += w1.x * v1.x + w1.y * v1.y + w1.z * v1.z + w1.w * v1.w;
            }
            S.s_g[0][t]       = acc00;
            S.s_g[0][t + 128] = acc01;
            S.s_g[1][t]       = acc10;
            S.s_g[1][t + 128] = acc11;
        }
        __syncthreads();
        {
            const int gi = t >> 6, k = t & 63;   // 2 graphs x 64 lanes = 128 threads
            float gc = sigmoidf_(S.s_g[gi][k]);
            float gf = sigmoidf_(S.s_g[gi][64 + k]);
            float gg = tanhf(S.s_g[gi][128 + k]);
            float go = sigmoidf_(S.s_g[gi][192 + k]);
            float cc = gf * S.s_c[gi][k] + gc * gg;
            S.s_c[gi][k] = cc;
            S.s_act[gi][k] = go * tanhf(cc);       // h (== q)
        }
        __syncthreads();
        if (step > 0) {
            // fixed shift for this step: M = ||q|| * sqrt(max row-norm^2)
            if (t < 2) {
                float q2 = 0.0f;
                #pragma unroll 16
                for (int k = 0; k < 64; k++) {
                    float hv = S.s_act[t][k];
                    q2 += hv * hv;
                }
                S.s_M[t] = sqrtf(q2 * S.s_mn[t]);
            }
            __syncthreads();
        }

        // ---- attention per graph: pipelined streaming pass ----
        for (int gi = 0; gi < ngr; gi++) {
            const float4 q0 = ((const float4*)S.s_act[gi])[4 * ql];
            const float4 q1 = ((const float4*)S.s_act[gi])[4 * ql + 1];
            const float4 q2 = ((const float4*)S.s_act[gi])[4 * ql + 2];
            const float4 q3 = ((const float4*)S.s_act[gi])[4 * ql + 3];
            const float M = S.s_M[gi];
            float m = -FLT_MAX, s = 0.0f, mn = 0.0f;
            float4 R0 = make_float4(0.f, 0.f, 0.f, 0.f);
            float4 R1 = R0, R2 = R0, R3 = R0;

            if (step == 0)
                attn_pass<true >(x, wstage, row0[gi], row1[gi], w, lane, q, ql, M,
                                 q0, q1, q2, q3, m, s, mn, R0, R1, R2, R3);
            else
                attn_pass<false>(x, wstage, row0[gi], row1[gi], w, lane, q, ql, M,
                                 q0, q1, q2, q3, m, s, mn, R0, R1, R2, R3);

            // combine NQ quad partials
            if (ql == 0) {
                S.s_rm[qd]  = (step == 0) ? m : M;
                S.s_rs[qd]  = s;
                S.s_rmn[qd] = mn;
            }
            ((float4*)S.s_rR[qd])[4 * ql]     = R0;
            ((float4*)S.s_rR[qd])[4 * ql + 1] = R1;
            ((float4*)S.s_rR[qd])[4 * ql + 2] = R2;
            ((float4*)S.s_rR[qd])[4 * ql + 3] = R3;
            __syncthreads();
            if (t < 64) {
                float Mx = -FLT_MAX;
                #pragma unroll 8
                for (int p = 0; p < NQ; p++) Mx = fmaxf(Mx, S.s_rm[p]);
                float st = 0.0f, Rk = 0.0f;
                #pragma unroll 8
                for (int p = 0; p < NQ; p++) {
                    float wq = __expf(S.s_rm[p] - Mx);
                    st += wq * S.s_rs[p];
                    Rk += wq * S.s_rR[p][t];
                }
                S.s_act[gi][64 + t] = Rk / fmaxf(st, 1e-16f);   // r
                if (step == 0 && t == 0) {
                    float mnx = 0.0f;
                    #pragma unroll 8
                    for (int p = 0; p < NQ; p++) mnx = fmaxf(mnx, S.s_rmn[p]);
                    S.s_mn[gi] = mnx;
                }
            }
            __syncthreads();
        }
    }

    // ---- final MLP per graph: 128 -> 256 (relu) -> 128 ----
    for (int gi = 0; gi < ngr; gi++) {
        {
            float acc0 = b1[t], acc1 = b1[t + 128];
            const float4* a = (const float4*)S.s_act[gi];
            #pragma unroll 8
            for (int k4 = 0; k4 < 32; k4++) {
                float4 w0 = d_W1p[k4 * 256 + t];
                float4 w1 = d_W1p[k4 * 256 + t + 128];
                float4 v  = a[k4];
                acc0 += w0.x * v.x + w0.y * v.y + w0.z * v.z + w0.w * v.w;
                acc1 += w1.x * v.x + w1.y * v.y + w1.z * v.z + w1.w * v.w;
            }
            S.s_g[0][t]       = fmaxf(acc0, 0.0f);
            S.s_g[0][t + 128] = fmaxf(acc1, 0.0f);
        }
        __syncthreads();
        {
            float acc = b2[t];
            const float4* hv = (const float4*)S.s_g[0];
            #pragma unroll 8
            for (int k4 = 0; k4 < 64; k4++) {
                float4 wv = d_W2p[k4 * 128 + t];
                float4 v  = hv[k4];
                acc += wv.x * v.x + wv.y * v.y + wv.z * v.z + wv.w * v.w;
            }
            out[(size_t)(g0 + gi) * 128 + t] = acc;
        }
        __syncthreads();
    }
}

extern "C" void kernel_launch(void* const* d_in, const int* in_sizes, int n_in,
                              void* d_out, int out_size) {
    const float* x     = (const float*)d_in[0];
    const int*   batch = (const int*)d_in[1];     // int32 (JAX x64 disabled)
    const float* Wih   = (const float*)d_in[2];
    const float* Whh   = (const float*)d_in[3];
    const float* bih   = (const float*)d_in[4];
    const float* bhh   = (const float*)d_in[5];
    const float* W1    = (const float*)d_in[6];
    const float* b1    = (const float*)d_in[7];
    const float* W2    = (const float*)d_in[8];
    const float* b2    = (const float*)d_in[9];

    int n = in_sizes[0] / HDIM;   // number of nodes

    static_assert(sizeof(Smem) <= 56 * 1024, "smem too big for occ 4");
    cudaFuncSetAttribute(fused_kernel, cudaFuncAttributeMaxDynamicSharedMemorySize,
                         (int)sizeof(Smem));

    prep_kernel<<<(n + 511) / 512, 512>>>(batch, n, Wih, Whh, bih, bhh, W1, W2);
    fused_kernel<<<CTAS, NTHR, sizeof(Smem)>>>(x, b1, b2, (float*)d_out, n);
}

// round 14
// speedup vs baseline: 1.6959x; 1.0626x over previous
#include <cuda_runtime.h>
#include <cuda_fp16.h>
#include <cuda_pipeline.h>
#include <cstdint>
#include <float.h>

#define NGRAPH 1024
#define HDIM   64
#define NMAX   1000000
#define CTAS   1024       // one CTA per graph; 148 SMs x occ 8 = 1184 slots -> one wave
#define NTHR   64
#define NW     2          // warps per CTA
#define NQ     16         // quads per CTA

// ---------------- device scratch (no allocation allowed) ----------------
__device__ float4 d_WL[32 * 256];    // packed LSTM weights: K=128 (h folded), [k4][n]
__device__ float  d_bsum[256];       // b_ih + b_hh
__device__ float4 d_W1p[32 * 256];   // W1 packed [k4][n]
__device__ float4 d_W2p[64 * 128];   // W2 packed [k4][n]
__device__ int    d_seg[NGRAPH + 1]; // segment row offsets
__device__ uint4  d_xh[NMAX * 8];    // fp16 copy of x (row = 64 halves = 8 uint4)

// dynamic shared memory layout (~18.4 KB -> 8 CTAs/SM)
struct Smem {
    char  stage[NW][6144];  // per-warp ring: fp32 3x2048B, fp16 6x1024B
    float s_act[128];       // [h(64) | r(64)]
    float s_c[64];
    float s_g[256];         // MLP hidden (final only)
    float s_rm[NQ];
    float s_rs[NQ];
    float s_rmn[NQ];        // per-quad max row-norm^2 partials (step 0)
    float s_h2[NW];         // per-warp ||h||^2 partials
    float s_mn;             // max row-norm^2
    float s_M;              // fixed softmax shift for this step
    float s_rR[NQ][64];
};

// ---------------- prep: segment offsets + weight packing ----------------
__global__ void prep_kernel(const int* __restrict__ batch, int n,
                            const float* __restrict__ Wih, const float* __restrict__ Whh,
                            const float* __restrict__ bih, const float* __restrict__ bhh,
                            const float* __restrict__ W1,  const float* __restrict__ W2) {
    int t = blockIdx.x * blockDim.x + threadIdx.x;
    if (t < n) {
        int b = batch[t];
        b = min(max(b, 0), NGRAPH - 1);
        int bp;
        if (t == 0) bp = -1;
        else {
            bp = batch[t - 1];
            bp = min(max(bp, 0), NGRAPH - 1);
        }
        for (int v = bp + 1; v <= b; v++) d_seg[v] = t;
        if (t == n - 1) {
            for (int v = b + 1; v <= NGRAPH; v++) d_seg[v] = n;
        }
    }
    // gates = h @ (W_ih[:, :64] + W_hh).T + r @ W_ih[:, 64:].T + (b_ih + b_hh)
    if (t < 32 * 256) {
        int k4 = t >> 8, nn = t & 255;
        float4 w; float* wp = (float*)&w;
        #pragma unroll
        for (int j = 0; j < 4; j++) {
            int k = k4 * 4 + j;
            if (k < 64) wp[j] = Wih[nn * 128 + k] + Whh[nn * 64 + k];
            else        wp[j] = Wih[nn * 128 + k];
        }
        d_WL[t] = w;
        float4 w1; float* w1p = (float*)&w1;
        #pragma unroll
        for (int j = 0; j < 4; j++) w1p[j] = W1[nn * 128 + k4 * 4 + j];
        d_W1p[t] = w1;
    }
    if (t < 256) d_bsum[t] = bih[t] + bhh[t];
    if (t < 64 * 128) {
        int k4 = t >> 7, nn = t & 127;
        float4 w; float* wp = (float*)&w;
        #pragma unroll
        for (int j = 0; j < 4; j++) wp[j] = W2[nn * 256 + k4 * 4 + j];
        d_W2p[t] = w;
    }
}

__device__ __forceinline__ float sigmoidf_(float v) {
    return 1.0f / (1.0f + __expf(-v));
}

// fill one 8-row slice into a staging slot via cp.async
template<bool FIRST>
__device__ __forceinline__ void fill_slice(char* slot, const float* __restrict__ x,
                                           int srow0, int r1, int lane) {
    int row = srow0 + (lane >> 2);
    row = min(row, r1 - 1);              // clamp: real data for tail rows (guarded later)
    if (FIRST) {
        const char* g = (const char*)(x + (size_t)row * HDIM) + (lane & 3) * 64;
        char* sdst = slot + (lane >> 2) * 256 + (lane & 3) * 64;
        #pragma unroll
        for (int u = 0; u < 4; u++)
            __pipeline_memcpy_async(sdst + u * 16, g + u * 16, 16);
    } else {
        const char* g = (const char*)(&d_xh[(size_t)row * 8]) + (lane & 3) * 32;
        char* sdst = slot + (lane >> 2) * 128 + (lane & 3) * 32;
        #pragma unroll
        for (int u = 0; u < 2; u++)
            __pipeline_memcpy_async(sdst + u * 16, g + u * 16, 16);
    }
}

// step-0 consumer: online softmax + max row-norm^2 tracking + fp16 copy store
__device__ __forceinline__ void consume_row_first(const char* slot, int row, int r1,
        int q, int ql,
        const float4& q0, const float4& q1, const float4& q2, const float4& q3,
        float& m, float& s, float& mn,
        float4& R0, float4& R1, float4& R2, float4& R3) {
    const bool act = (row < r1);
    const float4* p4 = (const float4*)(slot + q * 256 + ql * 64);
    float4 v0 = p4[0], v1 = p4[1], v2 = p4[2], v3 = p4[3];
    if (act) {   // fp16 copy for steps 1-4
        union { uint4 u; __half2 h[4]; } pk0, pk1;
        pk0.h[0] = __floats2half2_rn(v0.x, v0.y);
        pk0.h[1] = __floats2half2_rn(v0.z, v0.w);
        pk0.h[2] = __floats2half2_rn(v1.x, v1.y);
        pk0.h[3] = __floats2half2_rn(v1.z, v1.w);
        pk1.h[0] = __floats2half2_rn(v2.x, v2.y);
        pk1.h[1] = __floats2half2_rn(v2.z, v2.w);
        pk1.h[2] = __floats2half2_rn(v3.x, v3.y);
        pk1.h[3] = __floats2half2_rn(v3.z, v3.w);
        __stcs(&d_xh[(size_t)row * 8 + 2 * ql],     pk0.u);
        __stcs(&d_xh[(size_t)row * 8 + 2 * ql + 1], pk1.u);
    }
    float p = v0.x * q0.x + v0.y * q0.y + v0.z * q0.z + v0.w * q0.w
            + v1.x * q1.x + v1.y * q1.y + v1.z * q1.z + v1.w * q1.w
            + v2.x * q2.x + v2.y * q2.y + v2.z * q2.z + v2.w * q2.w
            + v3.x * q3.x + v3.y * q3.y + v3.z * q3.z + v3.w * q3.w;
    float n2 = v0.x * v0.x + v0.y * v0.y + v0.z * v0.z + v0.w * v0.w
             + v1.x * v1.x + v1.y * v1.y + v1.z * v1.z + v1.w * v1.w
             + v2.x * v2.x + v2.y * v2.y + v2.z * v2.z + v2.w * v2.w
             + v3.x * v3.x + v3.y * v3.y + v3.z * v3.z + v3.w * v3.w;
    p  += __shfl_xor_sync(0xffffffffu, p, 1);
    n2 += __shfl_xor_sync(0xffffffffu, n2, 1);
    p  += __shfl_xor_sync(0xffffffffu, p, 2);
    n2 += __shfl_xor_sync(0xffffffffu, n2, 2);
    if (act) {
        mn = fmaxf(mn, n2);
        if (p > m) {
            float sc = __expf(m - p);
            s *= sc;
            R0.x *= sc; R0.y *= sc; R0.z *= sc; R0.w *= sc;
            R1.x *= sc; R1.y *= sc; R1.z *= sc; R1.w *= sc;
            R2.x *= sc; R2.y *= sc; R2.z *= sc; R2.w *= sc;
            R3.x *= sc; R3.y *= sc; R3.z *= sc; R3.w *= sc;
            m = p;
        }
        float d = __expf(p - m);
        s += d;
        R0.x += d * v0.x; R0.y += d * v0.y; R0.z += d * v0.z; R0.w += d * v0.w;
        R1.x += d * v1.x; R1.y += d * v1.y; R1.z += d * v1.z; R1.w += d * v1.w;
        R2.x += d * v2.x; R2.y += d * v2.y; R2.z += d * v2.z; R2.w += d * v2.w;
        R3.x += d * v3.x; R3.y += d * v3.y; R3.z += d * v3.z; R3.w += d * v3.w;
    }
}

// steps 1-4 consumer: FIXED shift M -> straight-line, no carried compare chain
__device__ __forceinline__ void consume_row_fixed(const char* slot, int row, int r1,
        int q, int ql, float M,
        const float4& q0, const float4& q1, const float4& q2, const float4& q3,
        float& s, float4& R0, float4& R1, float4& R2, float4& R3) {
    const uint4* p4 = (const uint4*)(slot + q * 128 + ql * 32);
    union { uint4 u; __half2 h[4]; } pk0, pk1;
    pk0.u = p4[0];
    pk1.u = p4[1];
    float2 f;
    float4 v0, v1, v2, v3;
    f = __half22float2(pk0.h[0]); v0.x = f.x; v0.y = f.y;
    f = __half22float2(pk0.h[1]); v0.z = f.x; v0.w = f.y;
    f = __half22float2(pk0.h[2]); v1.x = f.x; v1.y = f.y;
    f = __half22float2(pk0.h[3]); v1.z = f.x; v1.w = f.y;
    f = __half22float2(pk1.h[0]); v2.x = f.x; v2.y = f.y;
    f = __half22float2(pk1.h[1]); v2.z = f.x; v2.w = f.y;
    f = __half22float2(pk1.h[2]); v3.x = f.x; v3.y = f.y;
    f = __half22float2(pk1.h[3]); v3.z = f.x; v3.w = f.y;
    float p = v0.x * q0.x + v0.y * q0.y + v0.z * q0.z + v0.w * q0.w
            + v1.x * q1.x + v1.y * q1.y + v1.z * q1.z + v1.w * q1.w
            + v2.x * q2.x + v2.y * q2.y + v2.z * q2.z + v2.w * q2.w
            + v3.x * q3.x + v3.y * q3.y + v3.z * q3.z + v3.w * q3.w;
    p += __shfl_xor_sync(0xffffffffu, p, 1);
    p += __shfl_xor_sync(0xffffffffu, p, 2);
    float d = (row < r1) ? __expf(p - M) : 0.0f;
    s += d;
    R0.x += d * v0.x; R0.y += d * v0.y; R0.z += d * v0.z; R0.w += d * v0.w;
    R1.x += d * v1.x; R1.y += d * v1.y; R1.z += d * v1.z; R1.w += d * v1.w;
    R2.x += d * v2.x; R2.y += d * v2.y; R2.z += d * v2.z; R2.w += d * v2.w;
    R3.x += d * v3.x; R3.y += d * v3.y; R3.z += d * v3.z; R3.w += d * v3.w;
}

// per-warp streaming attention pass with cp.async ring (no block syncs inside)
template<bool FIRST>
__device__ __forceinline__ void attn_pass(const float* __restrict__ x, char* wstage,
        int r0, int r1, int w, int lane, int q, int ql, float M,
        const float4& q0, const float4& q1, const float4& q2, const float4& q3,
        float& m, float& s, float& mn,
        float4& R0, float4& R1, float4& R2, float4& R3) {
    constexpr int S      = FIRST ? 3 : 6;
    constexpr int SLICE  = FIRST ? 2048 : 1024;
    constexpr int STRIDE = NW * 8;    // 16 rows per ring step
    const int wrow0 = r0 + w * 8;
    const int iters = (r1 > wrow0) ? ((r1 - wrow0 + STRIDE - 1) / STRIDE) : 0;
    #pragma unroll
    for (int j = 0; j < S - 1; j++) {
        if (j < iters) fill_slice<FIRST>(wstage + j * SLICE, x, wrow0 + j * STRIDE, r1, lane);
        __pipeline_commit();
    }
    int slot = 0;
    for (int j = 0; j < iters; j++) {
        __pipeline_wait_prior(S - 2);
        // issue next fill BEFORE the compute chain (target slot consumed 1 iter ago)
        int jn = j + S - 1;
        int sn = slot + S - 1; if (sn >= S) sn -= S;
        if (jn < iters) fill_slice<FIRST>(wstage + sn * SLICE, x, wrow0 + jn * STRIDE, r1, lane);
        __pipeline_commit();
        if (FIRST)
            consume_row_first(wstage + slot * SLICE, wrow0 + j * STRIDE + q, r1, q, ql,
                              q0, q1, q2, q3, m, s, mn, R0, R1, R2, R3);
        else
            consume_row_fixed(wstage + slot * SLICE, wrow0 + j * STRIDE + q, r1, q, ql, M,
                              q0, q1, q2, q3, s, R0, R1, R2, R3);
        __syncwarp();            // all lanes done reading slot before it is refilled
        slot++; if (slot == S) slot = 0;
    }
    __pipeline_wait_prior(0);
}

// ---------------- fused Set2Set + MLP: 1024 CTAs x 64 thr, ONE graph each ----------------
__global__ __launch_bounds__(NTHR, 8)
void fused_kernel(const float* __restrict__ x,
                  const float* __restrict__ b1,
                  const float* __restrict__ b2,
                  float* __restrict__ out, int n) {
    extern __shared__ char smraw[];
    Smem& S = *(Smem*)smraw;

    const int t    = threadIdx.x;
    const int g    = blockIdx.x;      // this CTA's graph
    const int w    = t >> 5;          // warp 0..1
    const int lane = t & 31;
    const int q    = lane >> 2;       // quad within warp 0..7
    const int ql   = t & 3;           // lane within quad
    const int qd   = t >> 2;          // global quad 0..15
    char* wstage   = S.stage[w];

    // init state
    {
        S.s_act[t]      = 0.0f;
        S.s_act[t + 64] = 0.0f;
        S.s_c[t]        = 0.0f;
        if (t == 0) { S.s_mn = 0.0f; S.s_M = 0.0f; }
    }
    int row0 = d_seg[g];
    int row1 = d_seg[g + 1];
    row0 = min(max(row0, 0), n);
    row1 = min(max(row1, row0), n);
    __syncthreads();

    for (int step = 0; step < 5; step++) {
        // ---- LSTM: 64 threads; thread t owns gates i,f,g,o for cell k=t ----
        {
            float ai = d_bsum[t], af = d_bsum[t + 64];
            float ag = d_bsum[t + 128], ao = d_bsum[t + 192];
            const float4* a0 = (const float4*)S.s_act;
            #pragma unroll 8
            for (int k4 = 0; k4 < 32; k4++) {
                float4 v  = a0[k4];
                float4 wi = d_WL[k4 * 256 + t];
                float4 wf = d_WL[k4 * 256 + t + 64];
                float4 wg = d_WL[k4 * 256 + t + 128];
                float4 wo = d_WL[k4 * 256 + t + 192];
                ai += wi.x * v.x + wi.y * v.y + wi.z * v.z + wi.w * v.w;
                af += wf.x * v.x + wf.y * v.y + wf.z * v.z + wf.w * v.w;
                ag += wg.x * v.x + wg.y * v.y + wg.z * v.z + wg.w * v.w;
                ao += wo.x * v.x + wo.y * v.y + wo.z * v.z + wo.w * v.w;
            }
            __syncthreads();   // everyone done reading s_act before overwrite
            float gi = sigmoidf_(ai);
            float gf = sigmoidf_(af);
            float gg = tanhf(ag);
            float go = sigmoidf_(ao);
            float cc = gf * S.s_c[t] + gi * gg;
            S.s_c[t] = cc;
            float hv = go * tanhf(cc);
            S.s_act[t] = hv;               // h (== q)
            // ||h||^2 warp partials
            float h2 = hv * hv;
            #pragma unroll
            for (int msk = 16; msk >= 1; msk >>= 1)
                h2 += __shfl_xor_sync(0xffffffffu, h2, msk);
            if (lane == 0) S.s_h2[w] = h2;
        }
        __syncthreads();
        if (t == 0)   // fixed shift: M = ||q|| * sqrt(max row-norm^2)
            S.s_M = sqrtf((S.s_h2[0] + S.s_h2[1]) * S.s_mn);
        __syncthreads();

        // ---- attention: pipelined streaming pass ----
        {
            const float4 q0 = ((const float4*)S.s_act)[4 * ql];
            const float4 q1 = ((const float4*)S.s_act)[4 * ql + 1];
            const float4 q2 = ((const float4*)S.s_act)[4 * ql + 2];
            const float4 q3 = ((const float4*)S.s_act)[4 * ql + 3];
            const float M = S.s_M;
            float m = -FLT_MAX, s = 0.0f, mn = 0.0f;
            float4 R0 = make_float4(0.f, 0.f, 0.f, 0.f);
            float4 R1 = R0, R2 = R0, R3 = R0;

            if (step == 0)
                attn_pass<true >(x, wstage, row0, row1, w, lane, q, ql, M,
                                 q0, q1, q2, q3, m, s, mn, R0, R1, R2, R3);
            else
                attn_pass<false>(x, wstage, row0, row1, w, lane, q, ql, M,
                                 q0, q1, q2, q3, m, s, mn, R0, R1, R2, R3);

            // combine NQ quad partials
            if (ql == 0) {
                S.s_rm[qd]  = (step == 0) ? m : M;
                S.s_rs[qd]  = s;
                S.s_rmn[qd] = mn;
            }
            ((float4*)S.s_rR[qd])[4 * ql]     = R0;
            ((float4*)S.s_rR[qd])[4 * ql + 1] = R1;
            ((float4*)S.s_rR[qd])[4 * ql + 2] = R2;
            ((float4*)S.s_rR[qd])[4 * ql + 3] = R3;
            __syncthreads();
            {
                float Mx = -FLT_MAX;
                #pragma unroll
                for (int p = 0; p < NQ; p++) Mx = fmaxf(Mx, S.s_rm[p]);
                float st = 0.0f, Rk = 0.0f;
                #pragma unroll
                for (int p = 0; p < NQ; p++) {
                    float wq = __expf(S.s_rm[p] - Mx);
                    st += wq * S.s_rs[p];
                    Rk += wq * S.s_rR[p][t];
                }
                float r = Rk / fmaxf(st, 1e-16f);
                float mnx = 0.0f;
                if (step == 0 && t == 0) {
                    #pragma unroll
                    for (int p = 0; p < NQ; p++) mnx = fmaxf(mnx, S.s_rmn[p]);
                }
                __syncthreads();           // reads of s_rR done before s_act overwrite
                S.s_act[64 + t] = r;
                if (step == 0 && t == 0) S.s_mn = mnx;
            }
            __syncthreads();
        }
    }

    // ---- final MLP: 128 -> 256 (relu) -> 128 ----
    {
        float a0 = b1[t], a1 = b1[t + 64], a2 = b1[t + 128], a3 = b1[t + 192];
        const float4* a = (const float4*)S.s_act;
        #pragma unroll 8
        for (int k4 = 0; k4 < 32; k4++) {
            float4 v  = a[k4];
            float4 w0 = d_W1p[k4 * 256 + t];
            float4 w1 = d_W1p[k4 * 256 + t + 64];
            float4 w2 = d_W1p[k4 * 256 + t + 128];
            float4 w3 = d_W1p[k4 * 256 + t + 192];
            a0 += w0.x * v.x + w0.y * v.y + w0.z * v.z + w0.w * v.w;
            a1 += w1.x * v.x + w1.y * v.y + w1.z * v.z + w1.w * v.w;
            a2 += w2.x * v.x + w2.y * v.y + w2.z * v.z + w2.w * v.w;
            a3 += w3.x * v.x + w3.y * v.y + w3.z * v.z + w3.w * v.w;
        }
        S.s_g[t]       = fmaxf(a0, 0.0f);
        S.s_g[t + 64]  = fmaxf(a1, 0.0f);
        S.s_g[t + 128] = fmaxf(a2, 0.0f);
        S.s_g[t + 192] = fmaxf(a3, 0.0f);
    }
    __syncthreads();
    {
        float o0 = b2[t], o1 = b2[t + 64];
        const float4* hv = (const float4*)S.s_g;
        #pragma unroll 8
        for (int k4 = 0; k4 < 64; k4++) {
            float4 v  = hv[k4];
            float4 w0 = d_W2p[k4 * 128 + t];
            float4 w1 = d_W2p[k4 * 128 + t + 64];
            o0 += w0.x * v.x + w0.y * v.y + w0.z * v.z + w0.w * v.w;
            o1 += w1.x * v.x + w1.y * v.y + w1.z * v.z + w1.w * v.w;
        }
        out[(size_t)g * 128 + t]      = o0;
        out[(size_t)g * 128 + t + 64] = o1;
    }
}

extern "C" void kernel_launch(void* const* d_in, const int* in_sizes, int n_in,
                              void* d_out, int out_size) {
    const float* x     = (const float*)d_in[0];
    const int*   batch = (const int*)d_in[1];     // int32 (JAX x64 disabled)
    const float* Wih   = (const float*)d_in[2];
    const float* Whh   = (const float*)d_in[3];
    const float* bih   = (const float*)d_in[4];
    const float* bhh   = (const float*)d_in[5];
    const float* W1    = (const float*)d_in[6];
    const float* b1    = (const float*)d_in[7];
    const float* W2    = (const float*)d_in[8];
    const float* b2    = (const float*)d_in[9];

    int n = in_sizes[0] / HDIM;   // number of nodes

    static_assert(sizeof(Smem) <= 28 * 1024, "smem too big for occ 8");
    cudaFuncSetAttribute(fused_kernel, cudaFuncAttributeMaxDynamicSharedMemorySize,
                         (int)sizeof(Smem));

    prep_kernel<<<(n + 511) / 512, 512>>>(batch, n, Wih, Whh, bih, bhh, W1, W2);
    fused_kernel<<<CTAS, NTHR, sizeof(Smem)>>>(x, b1, b2, (float*)d_out, n);
}